// round 2
// baseline (speedup 1.0000x reference)
#include <cuda_runtime.h>

// Problem constants (from reference): x[N,D] @ di[D,V] -> argmax over V -> float32 index
constexpr int D_DIM   = 2048;
constexpr int V_DIM   = 8192;
constexpr int VSPLIT  = 4;                 // split V across blockIdx.y for occupancy
constexpr int VCHUNK  = V_DIM / VSPLIT;    // 2048 cols per split
constexpr int BM = 128, BN = 128, BK = 16;
constexpr int TM = 8,  TN = 8;
constexpr int NTHREADS = 256;
constexpr int MAX_N   = 16384;
constexpr int ASTR = BM + 4;               // smem row stride (pad)
constexpr int BSTR = BN + 4;

// Scratch for V-split partial argmax (no cudaMalloc allowed)
__device__ float g_pmax[MAX_N * VSPLIT];
__device__ int   g_pidx[MAX_N * VSPLIT];

__global__ void __launch_bounds__(NTHREADS)
gemm_argmax_kernel(const float* __restrict__ x, const float* __restrict__ di)
{
    __shared__ float As[2][BK][ASTR];
    __shared__ float Bs[2][BK][BSTR];
    __shared__ float s_max[BM];
    __shared__ int   s_idx[BM];

    const int tid   = threadIdx.x;
    const int tx    = tid & 15;     // col group (TN cols each)
    const int ty    = tid >> 4;     // row group (TM rows each)
    const int m0    = blockIdx.x * BM;
    const int vbase = blockIdx.y * VCHUNK;

    if (tid < BM) { s_max[tid] = __int_as_float(0xff800000); s_idx[tid] = 0; }
    __syncthreads();

    // A-tile load map: 2 float4/thread. L = tid + 256*l -> row L/4, koff (L&3)*4
    const int arow0 = tid >> 2;            // rows 0..63   (l=0)
    const int arow1 = arow0 + 64;          // rows 64..127 (l=1)
    const int ak    = (tid & 3) * 4;       // k offset within BK
    // B-tile load map: L = tid + 256*l -> krow L/32, coloff (L&31)*4
    const int bk0 = tid >> 5;              // k rows 0..7
    const int bk1 = bk0 + 8;               // k rows 8..15
    const int bc  = (tid & 31) * 4;        // cols 0..124

    const float* xr0 = x + (size_t)(m0 + arow0) * D_DIM;
    const float* xr1 = x + (size_t)(m0 + arow1) * D_DIM;

    float acc[TM][TN];

    for (int n0 = 0; n0 < VCHUNK; n0 += BN) {
        const int nbase = vbase + n0;

        #pragma unroll
        for (int i = 0; i < TM; i++)
            #pragma unroll
            for (int j = 0; j < TN; j++) acc[i][j] = 0.f;

        // prologue: LDG k-chunk 0 into registers
        float4 aR0 = *(const float4*)(xr0 + ak);
        float4 aR1 = *(const float4*)(xr1 + ak);
        float4 bR0 = *(const float4*)(di + (size_t)bk0 * V_DIM + nbase + bc);
        float4 bR1 = *(const float4*)(di + (size_t)bk1 * V_DIM + nbase + bc);

        #pragma unroll 1
        for (int kc = 0; kc < D_DIM / BK; kc++) {
            const int st = kc & 1;
            // STS chunk kc (A transposed)
            As[st][ak + 0][arow0] = aR0.x;
            As[st][ak + 1][arow0] = aR0.y;
            As[st][ak + 2][arow0] = aR0.z;
            As[st][ak + 3][arow0] = aR0.w;
            As[st][ak + 0][arow1] = aR1.x;
            As[st][ak + 1][arow1] = aR1.y;
            As[st][ak + 2][arow1] = aR1.z;
            As[st][ak + 3][arow1] = aR1.w;
            *(float4*)&Bs[st][bk0][bc] = bR0;
            *(float4*)&Bs[st][bk1][bc] = bR1;

            // branchless prefetch of chunk kc+1 (clamped pointer on last iter;
            // values are discarded there, keeps hot loop free of BSSY/BSYNC)
            {
                const int kn = (kc + 1 < D_DIM / BK) ? (kc + 1) * BK : kc * BK;
                aR0 = *(const float4*)(xr0 + kn + ak);
                aR1 = *(const float4*)(xr1 + kn + ak);
                bR0 = *(const float4*)(di + (size_t)(kn + bk0) * V_DIM + nbase + bc);
                bR1 = *(const float4*)(di + (size_t)(kn + bk1) * V_DIM + nbase + bc);
            }
            __syncthreads();   // STS(kc) visible to all

            #pragma unroll
            for (int kk = 0; kk < BK; kk++) {
                float a[TM], b[TN];
                *(float4*)&a[0] = *(const float4*)&As[st][kk][ty * TM];
                *(float4*)&a[4] = *(const float4*)&As[st][kk][ty * TM + 4];
                *(float4*)&b[0] = *(const float4*)&Bs[st][kk][tx * TN];
                *(float4*)&b[4] = *(const float4*)&Bs[st][kk][tx * TN + 4];
                #pragma unroll
                for (int i = 0; i < TM; i++)
                    #pragma unroll
                    for (int j = 0; j < TN; j++)
                        acc[i][j] = fmaf(a[i], b[j], acc[i][j]);
            }
            __syncthreads();   // reads of stage st done before it is rewritten
        }

        // fused argmax over this BN chunk
        #pragma unroll
        for (int i = 0; i < TM; i++) {
            float v = acc[i][0];
            int   c = nbase + tx * TN;
            #pragma unroll
            for (int j = 1; j < TN; j++) {
                if (acc[i][j] > v) { v = acc[i][j]; c = nbase + tx * TN + j; }
            }
            // reduce across the 16 col-group lanes (tie -> smaller col, = first occurrence)
            #pragma unroll
            for (int off = 8; off > 0; off >>= 1) {
                float ov = __shfl_down_sync(0xffffffffu, v, off, 16);
                int   oc = __shfl_down_sync(0xffffffffu, c, off, 16);
                if (ov > v || (ov == v && oc < c)) { v = ov; c = oc; }
            }
            if (tx == 0) {
                const int r = ty * TM + i;   // single writer per row
                if (v > s_max[r] || (v == s_max[r] && c < s_idx[r])) {
                    s_max[r] = v; s_idx[r] = c;
                }
            }
        }
        __syncthreads();
    }

    if (tid < BM) {
        const int r = m0 + tid;
        g_pmax[r * VSPLIT + blockIdx.y] = s_max[tid];
        g_pidx[r * VSPLIT + blockIdx.y] = s_idx[tid];
    }
}

__global__ void combine_kernel(float* __restrict__ out, int Nrows)
{
    const int r = blockIdx.x * blockDim.x + threadIdx.x;
    if (r >= Nrows) return;
    float best = g_pmax[r * VSPLIT];
    int   bi   = g_pidx[r * VSPLIT];
    #pragma unroll
    for (int s = 1; s < VSPLIT; s++) {
        const float v = g_pmax[r * VSPLIT + s];
        const int   c = g_pidx[r * VSPLIT + s];
        if (v > best || (v == best && c < bi)) { best = v; bi = c; }
    }
    out[r] = (float)bi;
}

extern "C" void kernel_launch(void* const* d_in, const int* in_sizes, int n_in,
                              void* d_out, int out_size)
{
    const float* x  = (const float*)d_in[0];   // [N, D]
    const float* di = (const float*)d_in[1];   // [D, V]
    float* out = (float*)d_out;                // [N] float32 indices
    const int N = in_sizes[0] / D_DIM;         // 16384

    dim3 grid(N / BM, VSPLIT);
    gemm_argmax_kernel<<<grid, NTHREADS>>>(x, di);
    combine_kernel<<<(N + 255) / 256, 256>>>(out, N);
}

// round 4
// speedup vs baseline: 6.9412x; 6.9412x over previous
#include <cuda_runtime.h>
#include <cuda_bf16.h>
#include <cstdint>

// ======================= problem constants =======================
constexpr int N_ROWS = 16384;   // M
constexpr int D_DIM  = 2048;    // K
constexpr int V_DIM  = 8192;    // N (argmax axis)
constexpr int BM = 128, BN = 128, BK = 32;
constexpr int KITER = D_DIM / BK;         // 64
constexpr int MT_G = N_ROWS / BM;         // 128 grid.x
constexpr int NT_G = V_DIM / BN;          // 64 grid.y
constexpr int NSTAGE = 3;
constexpr int SLOTS = 4;                  // candidate slots per (row, tile)
constexpr float TAU = 1.5f;               // >= 2 * max bf16 dot error (~14 sigma)

// smem: 3 pipeline stages of (A 128x80B + B 128x80B), then reused for scores
constexpr int ASTRIDE = 80;                       // 64B data + 16B pad (ldmatrix conflict-free)
constexpr int STAGE_BYTES = 2 * BM * ASTRIDE;     // 20480
constexpr int SROW = 132;                         // score row stride (floats)
constexpr int SMEM_BYTES = BM * SROW * 4;         // 67584 > 3*STAGE_BYTES=61440

// ======================= device scratch (no cudaMalloc allowed) =======================
__device__ __nv_bfloat16 g_xb[(size_t)N_ROWS * D_DIM];    // x in bf16
__device__ __nv_bfloat16 g_dtb[(size_t)V_DIM * D_DIM];    // di^T bf16 (K-major)
__device__ float         g_dtf[(size_t)V_DIM * D_DIM];    // di^T fp32 (rescore)
__device__ float g_tmax[N_ROWS * NT_G];
__device__ int   g_cnt [N_ROWS * NT_G];
__device__ int   g_ccol[N_ROWS * NT_G * SLOTS];
__device__ float g_cval[N_ROWS * NT_G * SLOTS];

// ======================= helpers =======================
__device__ __forceinline__ uint32_t smem_u32(const void* p) {
    uint32_t a;
    asm("{ .reg .u64 t; cvta.to.shared.u64 t, %1; cvt.u32.u64 %0, t; }" : "=r"(a) : "l"(p));
    return a;
}
__device__ __forceinline__ void cp_async16(uint32_t dst, const void* src) {
    asm volatile("cp.async.cg.shared.global [%0], [%1], 16;" :: "r"(dst), "l"(src) : "memory");
}
__device__ __forceinline__ void cp_commit() {
    asm volatile("cp.async.commit_group;" ::: "memory");
}
template <int N> __device__ __forceinline__ void cp_wait() {
    asm volatile("cp.async.wait_group %0;" :: "n"(N) : "memory");
}
__device__ __forceinline__ void ldmx4(uint32_t& r0, uint32_t& r1, uint32_t& r2, uint32_t& r3,
                                      uint32_t addr) {
    asm volatile("ldmatrix.sync.aligned.m8n8.x4.shared.b16 {%0,%1,%2,%3}, [%4];"
                 : "=r"(r0), "=r"(r1), "=r"(r2), "=r"(r3) : "r"(addr));
}
__device__ __forceinline__ void mma16816(float& c0, float& c1, float& c2, float& c3,
                                         uint32_t a0, uint32_t a1, uint32_t a2, uint32_t a3,
                                         uint32_t b0, uint32_t b1) {
    asm volatile("mma.sync.aligned.m16n8k16.row.col.f32.bf16.bf16.f32 "
                 "{%0,%1,%2,%3}, {%4,%5,%6,%7}, {%8,%9}, {%0,%1,%2,%3};"
                 : "+f"(c0), "+f"(c1), "+f"(c2), "+f"(c3)
                 : "r"(a0), "r"(a1), "r"(a2), "r"(a3), "r"(b0), "r"(b1));
}

// ======================= conversion kernels =======================
__global__ void __launch_bounds__(256) conv_x_kernel(const float* __restrict__ x) {
    size_t i = (size_t)blockIdx.x * 256 + threadIdx.x;     // float4 index
    float4 v = ((const float4*)x)[i];
    __nv_bfloat162* o = (__nv_bfloat162*)g_xb;
    o[2 * i + 0] = __floats2bfloat162_rn(v.x, v.y);
    o[2 * i + 1] = __floats2bfloat162_rn(v.z, v.w);
}

__global__ void __launch_bounds__(256) transpose_di_kernel(const float* __restrict__ di) {
    __shared__ float t[32][33];
    const int v0 = blockIdx.x * 32, k0 = blockIdx.y * 32;
    const int tx = threadIdx.x, ty = threadIdx.y;
    #pragma unroll
    for (int i = 0; i < 4; i++)
        t[ty + 8 * i][tx] = di[(size_t)(k0 + ty + 8 * i) * V_DIM + v0 + tx];
    __syncthreads();
    #pragma unroll
    for (int i = 0; i < 4; i++) {
        float val = t[tx][ty + 8 * i];
        size_t o = (size_t)(v0 + ty + 8 * i) * D_DIM + k0 + tx;
        g_dtf[o] = val;
        g_dtb[o] = __float2bfloat16_rn(val);
    }
}

// ======================= HMMA GEMM + candidate epilogue =======================
__global__ void __launch_bounds__(256, 1) gemm_hmma_kernel() {
    extern __shared__ char smem[];
    const uint32_t sbase = smem_u32(smem);
    const int tid = threadIdx.x;
    const int wid = tid >> 5, lane = tid & 31;
    const int m0 = blockIdx.x * BM;
    const int v0 = blockIdx.y * BN;

    const int wm = wid >> 2;       // 0..1 : 64-row slab
    const int wn = wid & 3;        // 0..3 : 32-col slab

    // per-stage smem offsets
    uint32_t a_off[NSTAGE], b_off[NSTAGE];
    #pragma unroll
    for (int s = 0; s < NSTAGE; s++) {
        a_off[s] = sbase + s * STAGE_BYTES;
        b_off[s] = a_off[s] + BM * ASTRIDE;
    }

    // gmem load mapping: 2 x 16B per thread per operand per stage
    const int lrow = (tid + 0) >> 2;            // rows 0..63 (i=0), +64 (i=1)
    const int lc   = (tid & 3) * 16;            // byte chunk in 64B row
    const __nv_bfloat16* agp = g_xb + (size_t)(m0) * D_DIM;
    const __nv_bfloat16* bgp = g_dtb + (size_t)(v0) * D_DIM;

    float acc[4][4][4];
    #pragma unroll
    for (int i = 0; i < 4; i++)
        #pragma unroll
        for (int j = 0; j < 4; j++)
            #pragma unroll
            for (int e = 0; e < 4; e++) acc[i][j][e] = 0.f;

    // ldmatrix base addresses (lane-dependent constants)
    const int lm_row = lane & 15;
    const int lm_hi  = (lane >> 4) * 16;        // 16B half select

    auto load_stage = [&](int slot, int kc) {
        const size_t kb = (size_t)kc * BK;      // element offset in K
        #pragma unroll
        for (int i = 0; i < 2; i++) {
            const int row = lrow + 64 * i;
            cp_async16(a_off[slot] + row * ASTRIDE + lc,
                       agp + (size_t)row * D_DIM + kb + lc / 2);
            cp_async16(b_off[slot] + row * ASTRIDE + lc,
                       bgp + (size_t)row * D_DIM + kb + lc / 2);
        }
    };

    load_stage(0, 0); cp_commit();
    load_stage(1, 1); cp_commit();

    #pragma unroll 1
    for (int k = 0; k < KITER; k++) {
        cp_wait<1>();
        __syncthreads();
        if (k + 2 < KITER) load_stage((k + 2) % NSTAGE, k + 2);
        cp_commit();

        const int s = k % NSTAGE;
        const uint32_t abase = a_off[s] + (wm * 64 + lm_row) * ASTRIDE + lm_hi;
        const uint32_t bbase = b_off[s] + (wn * 32 + lm_row) * ASTRIDE + lm_hi;

        #pragma unroll
        for (int ks = 0; ks < 2; ks++) {
            const uint32_t ko = ks * 32;        // 16 bf16 = 32B per k-step
            uint32_t a[4][4];
            #pragma unroll
            for (int mt = 0; mt < 4; mt++)
                ldmx4(a[mt][0], a[mt][1], a[mt][2], a[mt][3],
                      abase + mt * 16 * ASTRIDE + ko);
            uint32_t b[2][4];
            #pragma unroll
            for (int nh = 0; nh < 2; nh++)
                ldmx4(b[nh][0], b[nh][1], b[nh][2], b[nh][3],
                      bbase + nh * 16 * ASTRIDE + ko);
            #pragma unroll
            for (int mt = 0; mt < 4; mt++)
                #pragma unroll
                for (int nt = 0; nt < 4; nt++) {
                    const uint32_t b0 = (nt & 1) ? b[nt >> 1][1] : b[nt >> 1][0];
                    const uint32_t b1 = (nt & 1) ? b[nt >> 1][3] : b[nt >> 1][2];
                    mma16816(acc[mt][nt][0], acc[mt][nt][1], acc[mt][nt][2], acc[mt][nt][3],
                             a[mt][0], a[mt][1], a[mt][2], a[mt][3], b0, b1);
                }
        }
    }
    cp_wait<0>();
    __syncthreads();   // pipeline stages dead; reuse smem for scores

    // dump accumulators: scores[row][col], row 0..127, col 0..127
    float* sc = (float*)smem;
    {
        const int rq = lane >> 2;          // 0..7
        const int cq = (lane & 3) * 2;     // 0,2,4,6
        #pragma unroll
        for (int mt = 0; mt < 4; mt++)
            #pragma unroll
            for (int nt = 0; nt < 4; nt++) {
                const int row = wm * 64 + mt * 16 + rq;
                const int col = wn * 32 + nt * 8 + cq;
                sc[(row + 0) * SROW + col + 0] = acc[mt][nt][0];
                sc[(row + 0) * SROW + col + 1] = acc[mt][nt][1];
                sc[(row + 8) * SROW + col + 0] = acc[mt][nt][2];
                sc[(row + 8) * SROW + col + 1] = acc[mt][nt][3];
            }
    }
    __syncthreads();

    // candidate scan: warp w owns rows w*16 .. w*16+15
    const int tix = blockIdx.y;
    for (int rr = wid * 16; rr < wid * 16 + 16; rr++) {
        float v[4];
        float mx = -3.4e38f;
        #pragma unroll
        for (int g = 0; g < 4; g++) {
            v[g] = sc[rr * SROW + g * 32 + lane];
            mx = fmaxf(mx, v[g]);
        }
        #pragma unroll
        for (int off = 16; off > 0; off >>= 1)
            mx = fmaxf(mx, __shfl_xor_sync(0xffffffffu, mx, off));
        const float thr = mx - TAU;
        const int gr = m0 + rr;
        const int base = (gr * NT_G + tix) * SLOTS;
        int cnt = 0;
        #pragma unroll
        for (int g = 0; g < 4; g++) {
            const bool hit = (v[g] >= thr);
            const uint32_t mask = __ballot_sync(0xffffffffu, hit);
            if (hit) {
                const int pos = cnt + __popc(mask & ((1u << lane) - 1u));
                if (pos < SLOTS) {
                    g_ccol[base + pos] = v0 + g * 32 + lane;
                    g_cval[base + pos] = v[g];
                }
            }
            cnt += __popc(mask);
        }
        if (lane == 0) {
            g_tmax[gr * NT_G + tix] = mx;
            g_cnt [gr * NT_G + tix] = min(cnt, SLOTS);
        }
    }
}

// ======================= combine + exact fp32 rescore =======================
__global__ void __launch_bounds__(256) rescore_kernel(const float* __restrict__ x,
                                                      float* __restrict__ out) {
    const int r = (blockIdx.x * 256 + threadIdx.x) >> 5;
    const int lane = threadIdx.x & 31;
    if (r >= N_ROWS) return;

    // global approx max over 64 tiles (2 per lane)
    float gm = fmaxf(g_tmax[r * NT_G + lane], g_tmax[r * NT_G + lane + 32]);
    #pragma unroll
    for (int off = 16; off > 0; off >>= 1)
        gm = fmaxf(gm, __shfl_xor_sync(0xffffffffu, gm, off));
    const float thr = gm - TAU;

    // count qualifying candidates
    int q = 0, mycol = 0x7fffffff;
    #pragma unroll
    for (int h = 0; h < 2; h++) {
        const int nt = lane + 32 * h;
        const int c_ = g_cnt[r * NT_G + nt];
        const int base = (r * NT_G + nt) * SLOTS;
        for (int s = 0; s < c_; s++) {
            if (g_cval[base + s] >= thr) {
                mycol = min(mycol, g_ccol[base + s]);
                q++;
            }
        }
    }
    int tot = q;
    int col1 = mycol;
    #pragma unroll
    for (int off = 16; off > 0; off >>= 1) {
        tot  += __shfl_xor_sync(0xffffffffu, tot, off);
        col1 = min(col1, __shfl_xor_sync(0xffffffffu, col1, off));
    }
    if (tot == 1) {
        if (lane == 0) out[r] = (float)col1;
        return;
    }

    // exact fp32 dots for every qualifying candidate
    float bestv = -3.4e38f;
    int bestc = 0x7fffffff;
    const float4* xr = (const float4*)(x + (size_t)r * D_DIM);
    for (int nt = 0; nt < NT_G; nt++) {
        const int c_ = g_cnt[r * NT_G + nt];
        const int base = (r * NT_G + nt) * SLOTS;
        for (int s = 0; s < c_; s++) {
            if (g_cval[base + s] < thr) continue;
            const int col = g_ccol[base + s];
            const float4* dv = (const float4*)(g_dtf + (size_t)col * D_DIM);
            float a_ = 0.f;
            #pragma unroll
            for (int i = 0; i < 16; i++) {
                float4 a = xr[lane + 32 * i];
                float4 b = dv[lane + 32 * i];
                a_ += a.x * b.x + a.y * b.y + a.z * b.z + a.w * b.w;
            }
            #pragma unroll
            for (int off = 16; off > 0; off >>= 1)
                a_ += __shfl_xor_sync(0xffffffffu, a_, off);
            if (a_ > bestv || (a_ == bestv && col < bestc)) { bestv = a_; bestc = col; }
        }
    }
    if (lane == 0) out[r] = (float)bestc;
}

// ======================= launch =======================
extern "C" void kernel_launch(void* const* d_in, const int* in_sizes, int n_in,
                              void* d_out, int out_size)
{
    const float* x  = (const float*)d_in[0];   // [N, D]
    const float* di = (const float*)d_in[1];   // [D, V]
    float* out = (float*)d_out;

    static bool attr_done = false;
    if (!attr_done) {
        cudaFuncSetAttribute(gemm_hmma_kernel,
                             cudaFuncAttributeMaxDynamicSharedMemorySize, SMEM_BYTES);
        attr_done = true;
    }

    conv_x_kernel<<<(N_ROWS * D_DIM / 4) / 256, 256>>>(x);
    transpose_di_kernel<<<dim3(V_DIM / 32, D_DIM / 32), dim3(32, 8)>>>(di);
    gemm_hmma_kernel<<<dim3(MT_G, NT_G), 256, SMEM_BYTES>>>();
    rescore_kernel<<<N_ROWS / 8, 256>>>(x, out);
}

// round 10
// speedup vs baseline: 7.3235x; 1.0551x over previous
#include <cuda_runtime.h>
#include <cuda_fp16.h>
#include <cstdint>

// ======================= problem constants =======================
constexpr int N_ROWS = 16384;   // M
constexpr int D_DIM  = 2048;    // K
constexpr int V_DIM  = 8192;    // N (argmax axis)
constexpr int BM = 128, BN = 128, BK = 32;
constexpr int KITER = D_DIM / BK;         // 64
constexpr int MT_G = N_ROWS / BM;         // 128
constexpr int NT_G = V_DIM / BN;          // 64
constexpr int NSTAGE = 3;
constexpr int SLOTS = 4;                  // candidate slots per (row, tile)
constexpr float TAU = 3.0f;               // ~12 sigma of f16-accum screen error

constexpr int ASTRIDE = 80;                       // 64B data + 16B pad (conflict-free ldmatrix)
constexpr int STAGE_BYTES = 2 * BM * ASTRIDE;     // 20480
constexpr int SMEM_BYTES = NSTAGE * STAGE_BYTES;  // 61440 -> 2+ CTAs/SM

// epilogue overlay offsets (reuses stage smem after mainloop)
constexpr int EP_RMAX = 0;                  // float[128][4]
constexpr int EP_THR  = EP_RMAX + 128 * 4 * 4;   // float[128]
constexpr int EP_CNT  = EP_THR + 128 * 4;        // int[128]

// ======================= device scratch (no cudaMalloc allowed) =======================
__device__ __half g_xh [(size_t)N_ROWS * D_DIM];   // x in f16
__device__ __half g_dth[(size_t)V_DIM * D_DIM];    // di^T f16 (K-major)
__device__ float  g_dtf[(size_t)V_DIM * D_DIM];    // di^T fp32 (rescore)
__device__ float g_tmax[N_ROWS * NT_G];
__device__ int   g_cnt [N_ROWS * NT_G];
__device__ int   g_ccol[N_ROWS * NT_G * SLOTS];
__device__ float g_cval[N_ROWS * NT_G * SLOTS];

// ======================= helpers =======================
__device__ __forceinline__ uint32_t smem_u32(const void* p) {
    uint32_t a;
    asm("{ .reg .u64 t; cvta.to.shared.u64 t, %1; cvt.u32.u64 %0, t; }" : "=r"(a) : "l"(p));
    return a;
}
__device__ __forceinline__ void cp_async16(uint32_t dst, const void* src) {
    asm volatile("cp.async.cg.shared.global [%0], [%1], 16;" :: "r"(dst), "l"(src) : "memory");
}
__device__ __forceinline__ void cp_commit() { asm volatile("cp.async.commit_group;" ::: "memory"); }
template <int N> __device__ __forceinline__ void cp_wait() {
    asm volatile("cp.async.wait_group %0;" :: "n"(N) : "memory");
}
__device__ __forceinline__ void ldmx4(uint32_t& r0, uint32_t& r1, uint32_t& r2, uint32_t& r3,
                                      uint32_t addr) {
    asm volatile("ldmatrix.sync.aligned.m8n8.x4.shared.b16 {%0,%1,%2,%3}, [%4];"
                 : "=r"(r0), "=r"(r1), "=r"(r2), "=r"(r3) : "r"(addr));
}
// f16 x f16 -> f16 accumulate (packed f16x2 c regs)
__device__ __forceinline__ void mma16816_f16(uint32_t& c0, uint32_t& c1,
                                             uint32_t a0, uint32_t a1, uint32_t a2, uint32_t a3,
                                             uint32_t b0, uint32_t b1) {
    asm volatile("mma.sync.aligned.m16n8k16.row.col.f16.f16.f16.f16 "
                 "{%0,%1}, {%2,%3,%4,%5}, {%6,%7}, {%0,%1};"
                 : "+r"(c0), "+r"(c1)
                 : "r"(a0), "r"(a1), "r"(a2), "r"(a3), "r"(b0), "r"(b1));
}

// ======================= conversion kernels =======================
__global__ void __launch_bounds__(256) conv_x_kernel(const float* __restrict__ x) {
    size_t i = (size_t)blockIdx.x * 256 + threadIdx.x;     // float4 index
    float4 v = ((const float4*)x)[i];
    __half2* o = (__half2*)g_xh;
    o[2 * i + 0] = __floats2half2_rn(v.x, v.y);
    o[2 * i + 1] = __floats2half2_rn(v.z, v.w);
}

__global__ void __launch_bounds__(256) transpose_di_kernel(const float* __restrict__ di) {
    __shared__ float t[32][33];
    const int v0 = blockIdx.x * 32, k0 = blockIdx.y * 32;
    const int tx = threadIdx.x, ty = threadIdx.y;
    #pragma unroll
    for (int i = 0; i < 4; i++)
        t[ty + 8 * i][tx] = di[(size_t)(k0 + ty + 8 * i) * V_DIM + v0 + tx];
    __syncthreads();
    #pragma unroll
    for (int i = 0; i < 4; i++) {
        float val = t[tx][ty + 8 * i];
        size_t o = (size_t)(v0 + ty + 8 * i) * D_DIM + k0 + tx;
        g_dtf[o] = val;
        g_dth[o] = __float2half_rn(val);
    }
}

// ======================= HMMA f16 GEMM + register-resident candidate epilogue =======================
__global__ void __launch_bounds__(256, 2) gemm_hmma_kernel() {
    extern __shared__ char smem[];
    const uint32_t sbase = smem_u32(smem);
    const int tid = threadIdx.x;
    const int wid = tid >> 5, lane = tid & 31;
    const int m0 = blockIdx.x * BM;
    const int v0 = blockIdx.y * BN;

    const int wm = wid >> 2;       // 0..1 : 64-row slab
    const int wn = wid & 3;        // 0..3 : 32-col slab

    uint32_t a_off[NSTAGE], b_off[NSTAGE];
    #pragma unroll
    for (int s = 0; s < NSTAGE; s++) {
        a_off[s] = sbase + s * STAGE_BYTES;
        b_off[s] = a_off[s] + BM * ASTRIDE;
    }

    const int lrow = tid >> 2;                  // rows 0..63 (i=0), +64 (i=1)
    const int lc   = (tid & 3) * 16;            // byte chunk in 64B row
    const __half* agp = g_xh  + (size_t)m0 * D_DIM;
    const __half* bgp = g_dth + (size_t)v0 * D_DIM;

    // f16 accumulators: [mt][nt][half] where half 0 = row rq, 1 = row rq+8
    uint32_t acc[4][4][2];
    const uint32_t zz = 0;
    #pragma unroll
    for (int i = 0; i < 4; i++)
        #pragma unroll
        for (int j = 0; j < 4; j++) { acc[i][j][0] = zz; acc[i][j][1] = zz; }

    const int lm_row = lane & 15;
    const int lm_hi  = (lane >> 4) * 16;

    auto load_stage = [&](int slot, int kc) {
        const size_t kb = (size_t)kc * BK;
        #pragma unroll
        for (int i = 0; i < 2; i++) {
            const int row = lrow + 64 * i;
            cp_async16(a_off[slot] + row * ASTRIDE + lc,
                       agp + (size_t)row * D_DIM + kb + lc / 2);
            cp_async16(b_off[slot] + row * ASTRIDE + lc,
                       bgp + (size_t)row * D_DIM + kb + lc / 2);
        }
    };

    load_stage(0, 0); cp_commit();
    load_stage(1, 1); cp_commit();

    #pragma unroll 1
    for (int k = 0; k < KITER; k++) {
        cp_wait<1>();
        __syncthreads();
        if (k + 2 < KITER) load_stage((k + 2) % NSTAGE, k + 2);
        cp_commit();

        const int s = k % NSTAGE;
        const uint32_t abase = a_off[s] + (wm * 64 + lm_row) * ASTRIDE + lm_hi;
        const uint32_t bbase = b_off[s] + (wn * 32 + lm_row) * ASTRIDE + lm_hi;

        #pragma unroll
        for (int ks = 0; ks < 2; ks++) {
            const uint32_t ko = ks * 32;
            uint32_t a[4][4];
            #pragma unroll
            for (int mt = 0; mt < 4; mt++)
                ldmx4(a[mt][0], a[mt][1], a[mt][2], a[mt][3],
                      abase + mt * 16 * ASTRIDE + ko);
            uint32_t b[2][4];
            #pragma unroll
            for (int nh = 0; nh < 2; nh++)
                ldmx4(b[nh][0], b[nh][1], b[nh][2], b[nh][3],
                      bbase + nh * 16 * ASTRIDE + ko);
            #pragma unroll
            for (int mt = 0; mt < 4; mt++)
                #pragma unroll
                for (int nt = 0; nt < 4; nt++) {
                    const uint32_t b0 = (nt & 1) ? b[nt >> 1][1] : b[nt >> 1][0];
                    const uint32_t b1 = (nt & 1) ? b[nt >> 1][3] : b[nt >> 1][2];
                    mma16816_f16(acc[mt][nt][0], acc[mt][nt][1],
                                 a[mt][0], a[mt][1], a[mt][2], a[mt][3], b0, b1);
                }
        }
    }
    cp_wait<0>();
    __syncthreads();   // stage smem dead; overlay epilogue arrays

    float* rmax4 = (float*)(smem + EP_RMAX);   // [row][wn]
    float* thr_s = (float*)(smem + EP_THR);    // [row]
    int*   cnt_s = (int*)  (smem + EP_CNT);    // [row]

    const int rq = lane >> 2;          // 0..7
    const int cq = (lane & 3) * 2;     // 0,2,4,6

    // per-thread per-row max over this warp's 32 cols, f16 -> f32
    #pragma unroll
    for (int mt = 0; mt < 4; mt++) {
        #pragma unroll
        for (int h = 0; h < 2; h++) {
            float m = -3.4e38f;
            #pragma unroll
            for (int nt = 0; nt < 4; nt++) {
                const __half2 hv = *(const __half2*)&acc[mt][nt][h];
                m = fmaxf(m, fmaxf(__low2float(hv), __high2float(hv)));
            }
            // reduce across the 4 lanes sharing this row (lane quads)
            #pragma unroll
            for (int off = 1; off < 4; off <<= 1)
                m = fmaxf(m, __shfl_xor_sync(0xffffffffu, m, off));
            if ((lane & 3) == 0) {
                const int row = wm * 64 + mt * 16 + rq + h * 8;
                rmax4[row * 4 + wn] = m;
            }
        }
    }
    __syncthreads();

    // rows 0..127: fold 4 warp maxima, publish threshold + tmax, zero counter
    if (tid < BM) {
        const float mx = fmaxf(fmaxf(rmax4[tid * 4 + 0], rmax4[tid * 4 + 1]),
                               fmaxf(rmax4[tid * 4 + 2], rmax4[tid * 4 + 3]));
        thr_s[tid] = mx - TAU;
        cnt_s[tid] = 0;
        g_tmax[(m0 + tid) * NT_G + blockIdx.y] = mx;
    }
    __syncthreads();

    // candidate extraction straight from registers
    #pragma unroll
    for (int mt = 0; mt < 4; mt++) {
        #pragma unroll
        for (int h = 0; h < 2; h++) {
            const int row = wm * 64 + mt * 16 + rq + h * 8;
            const float th = thr_s[row];
            const int base = ((m0 + row) * NT_G + blockIdx.y) * SLOTS;
            #pragma unroll
            for (int nt = 0; nt < 4; nt++) {
                const __half2 hv = *(const __half2*)&acc[mt][nt][h];
                const float v0f = __low2float(hv), v1f = __high2float(hv);
                if (v0f >= th) {
                    const int p = atomicAdd(&cnt_s[row], 1);
                    if (p < SLOTS) {
                        g_ccol[base + p] = v0 + wn * 32 + nt * 8 + cq;
                        g_cval[base + p] = v0f;
                    }
                }
                if (v1f >= th) {
                    const int p = atomicAdd(&cnt_s[row], 1);
                    if (p < SLOTS) {
                        g_ccol[base + p] = v0 + wn * 32 + nt * 8 + cq + 1;
                        g_cval[base + p] = v1f;
                    }
                }
            }
        }
    }
    __syncthreads();
    if (tid < BM)
        g_cnt[(m0 + tid) * NT_G + blockIdx.y] = min(cnt_s[tid], SLOTS);
}

// ======================= combine + exact fp32 rescore =======================
__global__ void __launch_bounds__(256) rescore_kernel(const float* __restrict__ x,
                                                      float* __restrict__ out) {
    const int r = (blockIdx.x * 256 + threadIdx.x) >> 5;
    const int lane = threadIdx.x & 31;
    if (r >= N_ROWS) return;

    float gm = fmaxf(g_tmax[r * NT_G + lane], g_tmax[r * NT_G + lane + 32]);
    #pragma unroll
    for (int off = 16; off > 0; off >>= 1)
        gm = fmaxf(gm, __shfl_xor_sync(0xffffffffu, gm, off));
    const float thr = gm - TAU;

    int q = 0, mycol = 0x7fffffff;
    #pragma unroll
    for (int h = 0; h < 2; h++) {
        const int nt = lane + 32 * h;
        const int c_ = g_cnt[r * NT_G + nt];
        const int base = (r * NT_G + nt) * SLOTS;
        for (int s = 0; s < c_; s++) {
            if (g_cval[base + s] >= thr) {
                mycol = min(mycol, g_ccol[base + s]);
                q++;
            }
        }
    }
    int tot = q;
    int col1 = mycol;
    #pragma unroll
    for (int off = 16; off > 0; off >>= 1) {
        tot  += __shfl_xor_sync(0xffffffffu, tot, off);
        col1 = min(col1, __shfl_xor_sync(0xffffffffu, col1, off));
    }
    if (tot == 1) {
        if (lane == 0) out[r] = (float)col1;
        return;
    }

    float bestv = -3.4e38f;
    int bestc = 0x7fffffff;
    const float4* xr = (const float4*)(x + (size_t)r * D_DIM);
    for (int nt = 0; nt < NT_G; nt++) {
        const int c_ = g_cnt[r * NT_G + nt];
        const int base = (r * NT_G + nt) * SLOTS;
        for (int s = 0; s < c_; s++) {
            if (g_cval[base + s] < thr) continue;
            const int col = g_ccol[base + s];
            const float4* dv = (const float4*)(g_dtf + (size_t)col * D_DIM);
            float a_ = 0.f;
            #pragma unroll
            for (int i = 0; i < 16; i++) {
                float4 a = xr[lane + 32 * i];
                float4 b = dv[lane + 32 * i];
                a_ += a.x * b.x + a.y * b.y + a.z * b.z + a.w * b.w;
            }
            #pragma unroll
            for (int off = 16; off > 0; off >>= 1)
                a_ += __shfl_xor_sync(0xffffffffu, a_, off);
            if (a_ > bestv || (a_ == bestv && col < bestc)) { bestv = a_; bestc = col; }
        }
    }
    if (lane == 0) out[r] = (float)bestc;
}

// ======================= launch =======================
extern "C" void kernel_launch(void* const* d_in, const int* in_sizes, int n_in,
                              void* d_out, int out_size)
{
    const float* x  = (const float*)d_in[0];   // [N, D]
    const float* di = (const float*)d_in[1];   // [D, V]
    float* out = (float*)d_out;

    static bool attr_done = false;
    if (!attr_done) {
        cudaFuncSetAttribute(gemm_hmma_kernel,
                             cudaFuncAttributeMaxDynamicSharedMemorySize, SMEM_BYTES);
        attr_done = true;
    }

    conv_x_kernel<<<(N_ROWS * D_DIM / 4) / 256, 256>>>(x);
    transpose_di_kernel<<<dim3(V_DIM / 32, D_DIM / 32), dim3(32, 8)>>>(di);
    gemm_hmma_kernel<<<dim3(MT_G, NT_G), 256, SMEM_BYTES>>>();
    rescore_kernel<<<N_ROWS / 8, 256>>>(x, out);
}